// round 10
// baseline (speedup 1.0000x reference)
#include <cuda_runtime.h>
#include <cstdint>

// SelMaxPool via bin + channel-phased gather:
//   pooled[m][c] = max( max_{j<pool} x[m*pool+j][c],
//                       max_{e active, dst[e]/pool == m} x[src[e]][c] )
// zero -> bin -> gather(half 0) -> gather(half 1) -> overflow.
// Each gather phase touches exactly one 128B L2 line per x row (unique
// working set 67MB << 126MB L2), so the ~3.5x row re-reads hit L2.
// Gather kernels carry ZERO scratch-maintenance side work and NO fences
// (R5/R7 showed a __threadfence/CCTL.IVALL tail poisons the whole kernel).

#define CH 64                 // channels
#define HALF 32               // channels per gather phase
#define M_MAX 131072          // max clusters supported by static scratch
#define CAP 96                // bin capacity per cluster (E[load] ~= 14)
#define OVF_CAP 262144

__device__ int g_cnt[M_MAX];
__device__ int g_bins[(size_t)M_MAX * CAP];
__device__ int g_ovf_cnt;
__device__ int g_ovf[2 * OVF_CAP];

__device__ __forceinline__ void atomicMaxFloat(float* addr, float val) {
    if (val >= 0.0f) atomicMax((int*)addr, __float_as_int(val));
    else             atomicMin((unsigned int*)addr, __float_as_uint(val));
}

__global__ void zero_counts_kernel(int M) {
    int i = blockIdx.x * blockDim.x + threadIdx.x;
    if (i < M) g_cnt[i] = 0;
    if (i == 0) g_ovf_cnt = 0;
}

__device__ __forceinline__ void bin_one(const int* __restrict__ src,
                                        const int* __restrict__ dst,
                                        const int* __restrict__ sel,
                                        int e, int thresh, int pool, int sh) {
    if (sel[e] >= thresh) return;
    int d = dst[e];
    int c = (sh >= 0) ? (d >> sh) : (d / pool);
    int s = src[e];
    int slot = atomicAdd(&g_cnt[c], 1);
    if (slot < CAP) {
        g_bins[(size_t)c * CAP + slot] = s;
    } else {
        int o = atomicAdd(&g_ovf_cnt, 1);
        if (o < OVF_CAP) { g_ovf[2 * o] = s; g_ovf[2 * o + 1] = c; }
    }
}

// Two edges per thread (e and e+E2) -> two independent atomic->store chains.
__global__ void bin_edges_kernel(const int* __restrict__ src,
                                 const int* __restrict__ dst,
                                 const int* __restrict__ sel,
                                 const int* __restrict__ ks_ptr,
                                 int E, int E2, int pool, int sh) {
    int e = blockIdx.x * blockDim.x + threadIdx.x;
    if (e >= E2) return;
    int k = ks_ptr[0];
    int thresh = k * k;
    bin_one(src, dst, sel, e, thresh, pool, sh);
    int e2 = e + E2;
    if (e2 < E) bin_one(src, dst, sel, e2, thresh, pool, sh);
}

// One warp per cluster, one channel half per launch (off = 0 or HALF).
// lane owns channel off+lane. Gathers in uniform clamped 8-deep batches
// (duplicates harmless under max) -> no serial tail. No side work.
__global__ void __launch_bounds__(256)
gather_half_kernel(const float* __restrict__ x,
                   float* __restrict__ out,
                   int M, int pool, int off) {
    int warp = (blockIdx.x * blockDim.x + threadIdx.x) >> 5;
    int lane = threadIdx.x & 31;
    if (warp >= M) return;
    const unsigned FULL = 0xffffffffu;
    int ol = off + lane;

    // Own rows (sequential across warps -> coalesced 128B-line stream).
    const float* xb = x + (size_t)warp * pool * CH + ol;
    float acc = __ldg(xb);
    for (int j = 1; j < pool; j++)
        acc = fmaxf(acc, __ldg(xb + (size_t)j * CH));

    int cnt = g_cnt[warp];
    if (cnt > CAP) cnt = CAP;

    if (cnt > 0) {
        size_t bbase = (size_t)warp * CAP;
        int last = cnt - 1;
        int b0 = g_bins[bbase + min(lane, last)];
        int b1 = (cnt > 32) ? g_bins[bbase + min(lane + 32, last)] : 0;
        int b2 = (cnt > 64) ? g_bins[bbase + min(lane + 64, last)] : 0;

        int chunks[3]; chunks[0] = b0; chunks[1] = b1; chunks[2] = b2;
        #pragma unroll
        for (int ch = 0; ch < 3; ch++) {
            int n = cnt - ch * 32;
            if (n <= 0) break;
            if (n > 32) n = 32;
            int b = chunks[ch];
            int nl = n - 1;
            int nb = (n + 7) & ~7;
            for (int i = 0; i < nb; i += 8) {
                int s0 = __shfl_sync(FULL, b, min(i,     nl));
                int s1 = __shfl_sync(FULL, b, min(i + 1, nl));
                int s2 = __shfl_sync(FULL, b, min(i + 2, nl));
                int s3 = __shfl_sync(FULL, b, min(i + 3, nl));
                int s4 = __shfl_sync(FULL, b, min(i + 4, nl));
                int s5 = __shfl_sync(FULL, b, min(i + 5, nl));
                int s6 = __shfl_sync(FULL, b, min(i + 6, nl));
                int s7 = __shfl_sync(FULL, b, min(i + 7, nl));
                float v0 = __ldg(x + (size_t)s0 * CH + ol);
                float v1 = __ldg(x + (size_t)s1 * CH + ol);
                float v2 = __ldg(x + (size_t)s2 * CH + ol);
                float v3 = __ldg(x + (size_t)s3 * CH + ol);
                float v4 = __ldg(x + (size_t)s4 * CH + ol);
                float v5 = __ldg(x + (size_t)s5 * CH + ol);
                float v6 = __ldg(x + (size_t)s6 * CH + ol);
                float v7 = __ldg(x + (size_t)s7 * CH + ol);
                float m0 = fmaxf(fmaxf(v0, v1), fmaxf(v2, v3));
                float m1 = fmaxf(fmaxf(v4, v5), fmaxf(v6, v7));
                acc = fmaxf(acc, fmaxf(m0, m1));
            }
        }
    }

    out[(size_t)warp * CH + ol] = acc;
}

// Rarely-run cleanup for bin overflow. Runs AFTER gathers init out.
__global__ void overflow_kernel(const float* __restrict__ x,
                                float* __restrict__ out) {
    int n = g_ovf_cnt; if (n > OVF_CAP) n = OVF_CAP;
    int warp = threadIdx.x >> 5;
    int lane = threadIdx.x & 31;
    const float2* xr = (const float2*)x;
    for (int i = warp; i < n; i += blockDim.x / 32) {
        int s = g_ovf[2 * i], c = g_ovf[2 * i + 1];
        float2 v = xr[(size_t)s * (CH / 2) + lane];
        float* o = out + (size_t)c * CH + lane * 2;
        atomicMaxFloat(o, v.x);
        atomicMaxFloat(o + 1, v.y);
    }
}

// ---- Fallback (M > M_MAX): direct atomic scatter path ----
__global__ void pool_init_kernel(const float* __restrict__ x,
                                 float* __restrict__ out, int total, int pool) {
    int t = blockIdx.x * blockDim.x + threadIdx.x;
    if (t >= total) return;
    int m = t >> 4, cg = t & 15;
    const float4* xr = (const float4*)x + (size_t)m * (pool * (CH / 4)) + cg;
    float4 r = xr[0];
    for (int j = 1; j < pool; j++) {
        float4 a = xr[(size_t)j * (CH / 4)];
        r.x = fmaxf(r.x, a.x); r.y = fmaxf(r.y, a.y);
        r.z = fmaxf(r.z, a.z); r.w = fmaxf(r.w, a.w);
    }
    ((float4*)out)[t] = r;
}

__global__ void edge_scatter_kernel(const float* __restrict__ x,
                                    const int* __restrict__ src,
                                    const int* __restrict__ dst,
                                    const int* __restrict__ sel,
                                    const int* __restrict__ ks_ptr,
                                    float* __restrict__ out,
                                    int E, int pool, int sh) {
    int gwarp = (blockIdx.x * blockDim.x + threadIdx.x) >> 5;
    int lane = threadIdx.x & 31;
    int base = gwarp * 32;
    if (base >= E) return;
    int k = ks_ptr[0]; int thresh = k * k;
    int e = base + lane;
    int s = 0, d = 0; bool act = false;
    if (e < E) { int se = sel[e]; s = src[e]; d = dst[e]; act = (se < thresh); }
    unsigned mask = __ballot_sync(0xffffffffu, act);
    while (mask) {
        int l = __ffs(mask) - 1; mask &= mask - 1;
        int ss = __shfl_sync(0xffffffffu, s, l);
        int dd = __shfl_sync(0xffffffffu, d, l);
        int c = (sh >= 0) ? (dd >> sh) : (dd / pool);
        float2 v = ((const float2*)(x + (size_t)ss * CH))[lane];
        float* o = out + (size_t)c * CH + lane * 2;
        atomicMaxFloat(o, v.x);
        atomicMaxFloat(o + 1, v.y);
    }
}

extern "C" void kernel_launch(void* const* d_in, const int* in_sizes, int n_in,
                              void* d_out, int out_size) {
    const float* x   = (const float*)d_in[0];
    const int*   ei  = (const int*)d_in[1];   // [2,E]: src row then dst row
    const int*   sel = (const int*)d_in[2];
    const int*   ks  = (const int*)d_in[4];
    float* out = (float*)d_out;

    int E = in_sizes[1] / 2;
    int N = in_sizes[3];          // cluster array length
    int M = out_size / CH;
    int pool = N / M;
    int sh = -1;
    for (int b = 0; b < 31; b++) if ((1 << b) == pool) { sh = b; break; }

    const int* src = ei;
    const int* dst = ei + E;

    if (M <= M_MAX) {
        zero_counts_kernel<<<(M + 255) / 256, 256>>>(M);
        int E2 = (E + 1) / 2;
        bin_edges_kernel<<<(E2 + 255) / 256, 256>>>(
            src, dst, sel, ks, E, E2, pool, sh);
        int threads = M * 32;
        int grid = (threads + 255) / 256;
        gather_half_kernel<<<grid, 256>>>(x, out, M, pool, 0);
        gather_half_kernel<<<grid, 256>>>(x, out, M, pool, HALF);
        overflow_kernel<<<1, 256>>>(x, out);
    } else {
        int totalA = M * (CH / 4);
        pool_init_kernel<<<(totalA + 255) / 256, 256>>>(x, out, totalA, pool);
        int warps = (E + 31) / 32;
        int threads = warps * 32;
        edge_scatter_kernel<<<(threads + 255) / 256, 256>>>(
            x, src, dst, sel, ks, out, E, pool, sh);
    }
}

// round 15
// speedup vs baseline: 1.2604x; 1.2604x over previous
#include <cuda_runtime.h>
#include <cstdint>

// SelMaxPool via bin + gather (single-phase, dual-row float4 gather):
//   pooled[m][c] = max( max_{j<pool} x[m*pool+j][c],
//                       max_{e active, dst[e]/pool == m} x[src[e]][c] )
// bin -> gather -> overflow+zero.  (zero kernel folded into the cold
// overflow kernel; scratch statically zeroed for call 1, each call leaves
// it zeroed for the next graph replay.)
// Gather: one warp per cluster; lanes 0-15 cover one row as float4, lanes
// 16-31 a second row -> each load instruction moves 512B / 2 rows; clamped
// 8-deep batches (duplicates harmless under max) -> no serial tail; the two
// half-warp accumulators merge via shfl_xor(16). NO side work in the gather.

#define CH 64                 // channels (64 floats = 16 float4 per row)
#define M_MAX 131072          // max clusters supported by static scratch
#define CAP 96                // bin capacity per cluster (E[load] ~= 14)
#define OVF_CAP 262144

__device__ int g_cnt[M_MAX];
__device__ int g_bins[(size_t)M_MAX * CAP];
__device__ int g_ovf_cnt;
__device__ int g_ovf[2 * OVF_CAP];

__device__ __forceinline__ void atomicMaxFloat(float* addr, float val) {
    if (val >= 0.0f) atomicMax((int*)addr, __float_as_int(val));
    else             atomicMin((unsigned int*)addr, __float_as_uint(val));
}

__global__ void bin_edges_kernel(const int* __restrict__ src,
                                 const int* __restrict__ dst,
                                 const int* __restrict__ sel,
                                 const int* __restrict__ ks_ptr,
                                 int E, int pool, int sh) {
    int e = blockIdx.x * blockDim.x + threadIdx.x;
    if (e >= E) return;
    int k = ks_ptr[0];
    if (sel[e] >= k * k) return;
    int d = dst[e];
    int c = (sh >= 0) ? (d >> sh) : (d / pool);
    int s = src[e];
    int slot = atomicAdd(&g_cnt[c], 1);
    if (slot < CAP) {
        g_bins[(size_t)c * CAP + slot] = s;
    } else {
        int o = atomicAdd(&g_ovf_cnt, 1);
        if (o < OVF_CAP) { g_ovf[2 * o] = s; g_ovf[2 * o + 1] = c; }
    }
}

__device__ __forceinline__ float4 fmax4(float4 a, float4 b) {
    a.x = fmaxf(a.x, b.x); a.y = fmaxf(a.y, b.y);
    a.z = fmaxf(a.z, b.z); a.w = fmaxf(a.w, b.w);
    return a;
}

// One warp per cluster. half = lane>>4 selects which of 2 concurrent rows
// this lane helps load; hl = lane&15 is the float4 position within the row.
__global__ void __launch_bounds__(256)
gather_max_kernel(const float* __restrict__ x,
                  float* __restrict__ out,
                  int M, int pool) {
    int warp = (blockIdx.x * blockDim.x + threadIdx.x) >> 5;
    int lane = threadIdx.x & 31;
    if (warp >= M) return;
    const unsigned FULL = 0xffffffffu;
    int half = lane >> 4;
    int hl = lane & 15;
    const float4* __restrict__ xr = (const float4*)x;  // 16 float4 per row

    // Own rows, two at a time (row index clamped for small/odd pool;
    // duplicate reads are harmless under max).
    size_t obase = (size_t)warp * pool;
    int pl = pool - 1;
    float4 acc = __ldg(&xr[(obase + min(half, pl)) * 16 + hl]);
    for (int j = 2; j < pool; j += 2)
        acc = fmax4(acc, __ldg(&xr[(obase + min(j + half, pl)) * 16 + hl]));

    int cnt = g_cnt[warp];
    if (cnt > CAP) cnt = CAP;

    if (cnt > 0) {
        size_t bbase = (size_t)warp * CAP;
        int last = cnt - 1;
        // Clamped prefetch: every lane's slot index is valid.
        int b0 = g_bins[bbase + min(lane, last)];
        int b1 = (cnt > 32) ? g_bins[bbase + min(lane + 32, last)] : 0;
        int b2 = (cnt > 64) ? g_bins[bbase + min(lane + 64, last)] : 0;

        int chunks[3]; chunks[0] = b0; chunks[1] = b1; chunks[2] = b2;
        #pragma unroll
        for (int ch = 0; ch < 3; ch++) {
            int n = cnt - ch * 32;
            if (n <= 0) break;
            if (n > 32) n = 32;
            int b = chunks[ch];
            int nl = n - 1;
            int nb = (n + 15) & ~15;        // round up to multiple of 16
            for (int i = 0; i < nb; i += 16) {
                // 8 loads in flight, each covering 2 rows (512B).
                int s0 = __shfl_sync(FULL, b, min(i +      half, nl));
                int s1 = __shfl_sync(FULL, b, min(i + 2  + half, nl));
                int s2 = __shfl_sync(FULL, b, min(i + 4  + half, nl));
                int s3 = __shfl_sync(FULL, b, min(i + 6  + half, nl));
                int s4 = __shfl_sync(FULL, b, min(i + 8  + half, nl));
                int s5 = __shfl_sync(FULL, b, min(i + 10 + half, nl));
                int s6 = __shfl_sync(FULL, b, min(i + 12 + half, nl));
                int s7 = __shfl_sync(FULL, b, min(i + 14 + half, nl));
                float4 v0 = __ldg(&xr[(size_t)s0 * 16 + hl]);
                float4 v1 = __ldg(&xr[(size_t)s1 * 16 + hl]);
                float4 v2 = __ldg(&xr[(size_t)s2 * 16 + hl]);
                float4 v3 = __ldg(&xr[(size_t)s3 * 16 + hl]);
                float4 v4 = __ldg(&xr[(size_t)s4 * 16 + hl]);
                float4 v5 = __ldg(&xr[(size_t)s5 * 16 + hl]);
                float4 v6 = __ldg(&xr[(size_t)s6 * 16 + hl]);
                float4 v7 = __ldg(&xr[(size_t)s7 * 16 + hl]);
                float4 m0 = fmax4(fmax4(v0, v1), fmax4(v2, v3));
                float4 m1 = fmax4(fmax4(v4, v5), fmax4(v6, v7));
                acc = fmax4(acc, fmax4(m0, m1));
            }
        }
    }

    // Merge the two half-warp accumulators (channels are identical; rows differ).
    acc.x = fmaxf(acc.x, __shfl_xor_sync(FULL, acc.x, 16));
    acc.y = fmaxf(acc.y, __shfl_xor_sync(FULL, acc.y, 16));
    acc.z = fmaxf(acc.z, __shfl_xor_sync(FULL, acc.z, 16));
    acc.w = fmaxf(acc.w, __shfl_xor_sync(FULL, acc.w, 16));

    if (half == 0)
        ((float4*)out)[(size_t)warp * 16 + hl] = acc;
}

// Cold-path kernel: handles bin overflow (normally empty) AND re-zeroes the
// scratch counters for the next graph replay. Runs AFTER gather inits out.
__global__ void overflow_zero_kernel(const float* __restrict__ x,
                                     float* __restrict__ out, int M) {
    int gtid = blockIdx.x * blockDim.x + threadIdx.x;
    if (gtid < M) g_cnt[gtid] = 0;

    if (blockIdx.x == 0) {
        int n = g_ovf_cnt; if (n > OVF_CAP) n = OVF_CAP;
        int warp = threadIdx.x >> 5;
        int lane = threadIdx.x & 31;
        const float2* xr = (const float2*)x;
        for (int i = warp; i < n; i += blockDim.x / 32) {
            int s = g_ovf[2 * i], c = g_ovf[2 * i + 1];
            float2 v = xr[(size_t)s * (CH / 2) + lane];
            float* o = out + (size_t)c * CH + lane * 2;
            atomicMaxFloat(o, v.x);
            atomicMaxFloat(o + 1, v.y);
        }
        __syncthreads();
        if (threadIdx.x == 0) g_ovf_cnt = 0;
    }
}

// ---- Fallback (M > M_MAX): direct atomic scatter path ----
__global__ void pool_init_kernel(const float* __restrict__ x,
                                 float* __restrict__ out, int total, int pool) {
    int t = blockIdx.x * blockDim.x + threadIdx.x;
    if (t >= total) return;
    int m = t >> 4, cg = t & 15;
    const float4* xr = (const float4*)x + (size_t)m * (pool * (CH / 4)) + cg;
    float4 r = xr[0];
    for (int j = 1; j < pool; j++) {
        float4 a = xr[(size_t)j * (CH / 4)];
        r.x = fmaxf(r.x, a.x); r.y = fmaxf(r.y, a.y);
        r.z = fmaxf(r.z, a.z); r.w = fmaxf(r.w, a.w);
    }
    ((float4*)out)[t] = r;
}

__global__ void edge_scatter_kernel(const float* __restrict__ x,
                                    const int* __restrict__ src,
                                    const int* __restrict__ dst,
                                    const int* __restrict__ sel,
                                    const int* __restrict__ ks_ptr,
                                    float* __restrict__ out,
                                    int E, int pool, int sh) {
    int gwarp = (blockIdx.x * blockDim.x + threadIdx.x) >> 5;
    int lane = threadIdx.x & 31;
    int base = gwarp * 32;
    if (base >= E) return;
    int k = ks_ptr[0]; int thresh = k * k;
    int e = base + lane;
    int s = 0, d = 0; bool act = false;
    if (e < E) { int se = sel[e]; s = src[e]; d = dst[e]; act = (se < thresh); }
    unsigned mask = __ballot_sync(0xffffffffu, act);
    while (mask) {
        int l = __ffs(mask) - 1; mask &= mask - 1;
        int ss = __shfl_sync(0xffffffffu, s, l);
        int dd = __shfl_sync(0xffffffffu, d, l);
        int c = (sh >= 0) ? (dd >> sh) : (dd / pool);
        float2 v = ((const float2*)(x + (size_t)ss * CH))[lane];
        float* o = out + (size_t)c * CH + lane * 2;
        atomicMaxFloat(o, v.x);
        atomicMaxFloat(o + 1, v.y);
    }
}

extern "C" void kernel_launch(void* const* d_in, const int* in_sizes, int n_in,
                              void* d_out, int out_size) {
    const float* x   = (const float*)d_in[0];
    const int*   ei  = (const int*)d_in[1];   // [2,E]: src row then dst row
    const int*   sel = (const int*)d_in[2];
    const int*   ks  = (const int*)d_in[4];
    float* out = (float*)d_out;

    int E = in_sizes[1] / 2;
    int N = in_sizes[3];          // cluster array length
    int M = out_size / CH;
    int pool = N / M;
    int sh = -1;
    for (int b = 0; b < 31; b++) if ((1 << b) == pool) { sh = b; break; }

    const int* src = ei;
    const int* dst = ei + E;

    if (M <= M_MAX) {
        bin_edges_kernel<<<(E + 255) / 256, 256>>>(src, dst, sel, ks, E, pool, sh);
        int threads = M * 32;
        gather_max_kernel<<<(threads + 255) / 256, 256>>>(x, out, M, pool);
        overflow_zero_kernel<<<(M + 255) / 256, 256>>>(x, out, M);
    } else {
        int totalA = M * (CH / 4);
        pool_init_kernel<<<(totalA + 255) / 256, 256>>>(x, out, totalA, pool);
        int warps = (E + 31) / 32;
        int threads = warps * 32;
        edge_scatter_kernel<<<(threads + 255) / 256, 256>>>(
            x, src, dst, sel, ks, out, E, pool, sh);
    }
}